// round 5
// baseline (speedup 1.0000x reference)
#include <cuda_runtime.h>
#include <cstdint>

#define SVC_N  20000
#define INST_N 100000
#define NODE_N 10000
#define HID    128

#define E_SC_MAX 640000
#define E_IN_MAX 200000
#define E_NI_MAX 200000

// ---- count/rsqrt layout offsets ----
#define OFF_A_S 0
#define OFF_A_D 20000
#define OFF_B_S 40000
#define OFF_B_D 140000
#define OFF_C_S 150000
#define OFF_C_D 160000
#define CNT_TOTAL 260000

#define NB_A 20
#define NB_B 10
#define NB_C 98
#define NB_TOTAL (NB_A + NB_B + NB_C)   // 128 scan blocks

// persistent fused-preamble grid
#define FBLK 255
#define FTHR 1024
#define FTOT (FBLK * FTHR)               // 261120 threads

// ---- scratch ----
__device__ int      g_cnt[CNT_TOTAL];    // zero at load; re-zeroed in scatter phase
__device__ float    g_rs[CNT_TOTAL];
__device__ int      g_offA[SVC_N + 1];
__device__ int      g_offB[NODE_N + 1];
__device__ int      g_offC[INST_N + 1];
__device__ int      g_curA[SVC_N];
__device__ int      g_curB[NODE_N];
__device__ int      g_curC[INST_N];
__device__ int      g_eA[E_SC_MAX];
__device__ int      g_eB[E_IN_MAX];
__device__ int      g_eC[E_NI_MAX];
__device__ int      g_bsum[384];
__device__ unsigned g_bar_ctr;           // monotone grid-barrier counter
__device__ float    g_aggA[(size_t)SVC_N * HID];
__device__ float    g_aggB[(size_t)NODE_N * HID];
__device__ float    g_hC[(size_t)NODE_N * HID];

// ============================================================================
// Grid barrier: monotone counter, replay-safe (never reset; 2^32/3 replays).
// All FBLK blocks are co-resident (one wave), so spinning cannot deadlock.
// ============================================================================
__device__ __forceinline__ void grid_bar() {
    __syncthreads();
    if (threadIdx.x == 0) {
        __threadfence();
        unsigned old = atomicAdd(&g_bar_ctr, 1u);
        unsigned target = (old / FBLK + 1u) * FBLK;
        while (*((volatile unsigned*)&g_bar_ctr) < target) { }
        __threadfence();
    }
    __syncthreads();
}

// ============================================================================
// Fused preamble: hist -> scan(+rsqrt) -> prefix -> scatter, one kernel.
// ============================================================================
__global__ void __launch_bounds__(FTHR, 2) fused_pre_k(
    const int* __restrict__ sA, const int* __restrict__ dA, int eA,
    const int* __restrict__ sB, const int* __restrict__ dB, int eB,
    const int* __restrict__ sC, const int* __restrict__ dC, int eC,
    int* __restrict__ cnt, float* __restrict__ rs,
    int* __restrict__ offA, int* __restrict__ offB, int* __restrict__ offC,
    int* __restrict__ curA, int* __restrict__ curB, int* __restrict__ curC,
    int* __restrict__ elA, int* __restrict__ elB, int* __restrict__ elC) {
    int tid = threadIdx.x, bid = blockIdx.x;
    int t = bid * FTHR + tid;
    int eAB = eA + eB;
    int eTot = eAB + eC;

    // ---------------- phase 1: degree histogram (cnt pre-zeroed) ----------------
    for (int j = t; j < eTot; j += FTOT) {
        int s, d, so, dof;
        if (j < eA)       { s = __ldg(sA + j);       d = __ldg(dA + j);       so = OFF_A_S; dof = OFF_A_D; }
        else if (j < eAB) { s = __ldg(sB + j - eA);  d = __ldg(dB + j - eA);  so = OFF_B_S; dof = OFF_B_D; }
        else              { s = __ldg(sC + j - eAB); d = __ldg(dC + j - eAB); so = OFF_C_S; dof = OFF_C_D; }
        atomicAdd(&cnt[so + s], 1);
        atomicAdd(&cnt[dof + d], 1);
    }
    grid_bar();   // B1: counts complete

    // ---------------- phase 2a: local scans + rsqrt, publish aggregates --------
    __shared__ int wsum[32];
    int seg = 0, chunk = 0, n = 0, E = 0, cntoff = 0;
    int *off = nullptr, *cur = nullptr;
    int v = 0, incl = 0;

    if (bid < NB_TOTAL) {
        if (bid < NB_A)              { seg = 0; chunk = bid;               n = SVC_N;  E = eA; cntoff = OFF_A_D; off = offA; cur = curA; }
        else if (bid < NB_A + NB_B)  { seg = 1; chunk = bid - NB_A;        n = NODE_N; E = eB; cntoff = OFF_B_D; off = offB; cur = curB; }
        else                         { seg = 2; chunk = bid - NB_A - NB_B; n = INST_N; E = eC; cntoff = OFF_C_D; off = offC; cur = curC; }

        int gid = chunk * FTHR + tid;
        v = (gid < n) ? cnt[cntoff + gid] : 0;
        if (gid < n) rs[cntoff + gid] = rsqrtf((float)(v > 0 ? v : 1));

        int lane = tid & 31, w = tid >> 5;
        int x = v;
#pragma unroll
        for (int o = 1; o < 32; o <<= 1) {
            int y = __shfl_up_sync(0xffffffffu, x, o);
            if (lane >= o) x += y;
        }
        if (lane == 31) wsum[w] = x;
        __syncthreads();
        if (w == 0) {
            int tt = wsum[lane];
#pragma unroll
            for (int o = 1; o < 32; o <<= 1) {
                int y = __shfl_up_sync(0xffffffffu, tt, o);
                if (lane >= o) tt += y;
            }
            wsum[lane] = tt;
        }
        __syncthreads();
        incl = x + (w > 0 ? wsum[w - 1] : 0);
        if (tid == 0) g_bsum[seg * 128 + chunk] = wsum[31];
    } else {
        // pure rsqrt over src ranges (130000 entries)
        int j = (bid - NB_TOTAL) * FTHR + tid;
        if (j < 130000) {
            int idx;
            if (j < 20000)       idx = OFF_A_S + j;
            else if (j < 120000) idx = OFF_B_S + (j - 20000);
            else                 idx = OFF_C_S + (j - 120000);
            int c = cnt[idx];
            rs[idx] = rsqrtf((float)(c > 0 ? c : 1));
        }
    }
    grid_bar();   // B2: aggregates published

    // ---------------- phase 2b: block prefix + write off/cur --------------------
    if (bid < NB_TOTAL) {
        int lane = tid & 31, w = tid >> 5;
        int segbase = seg * 128;
        int p = (tid < chunk) ? __ldg(&g_bsum[segbase + tid]) : 0;
        if (tid < 128) {
#pragma unroll
            for (int o = 16; o > 0; o >>= 1) p += __shfl_down_sync(0xffffffffu, p, o);
        }
        __shared__ int warp_p[4];
        __shared__ int s_pre;
        if (tid < 128 && lane == 0) warp_p[w] = p;
        __syncthreads();
        if (tid == 0) s_pre = warp_p[0] + warp_p[1] + warp_p[2] + warp_p[3];
        __syncthreads();
        int gid = chunk * FTHR + tid;
        if (gid < n) {
            int o = s_pre + incl - v;
            off[gid] = o;
            cur[gid] = o;
        }
        if (chunk == 0 && tid == 0) off[n] = E;
    }
    grid_bar();   // B3: cur initialized

    // ---------------- phase 3: scatter + cnt re-zero ---------------------------
    if (t < CNT_TOTAL) cnt[t] = 0;   // cnt fully consumed in phase 2a
    for (int j = t; j < eTot; j += FTOT) {
        if (j < eA) {
            int p = atomicAdd(&curA[__ldg(dA + j)], 1);
            elA[p] = __ldg(sA + j);
        } else if (j < eAB) {
            int jj = j - eA;
            int p = atomicAdd(&curB[__ldg(dB + jj)], 1);
            elB[p] = __ldg(sB + jj);
        } else {
            int jj = j - eAB;
            int p = atomicAdd(&curC[__ldg(dC + jj)], 1);
            elC[p] = __ldg(sC + jj);
        }
    }
}

// ============================================================================
// Combined aggregation: one warp per dst row across ALL three convs.
// ============================================================================
__global__ void __launch_bounds__(256) agg_all_k(
    const float* __restrict__ svc_feat, const float* __restrict__ inst_feat,
    const float* __restrict__ hC, const float* __restrict__ rs,
    const int* __restrict__ offA, const int* __restrict__ elA,
    const int* __restrict__ offB, const int* __restrict__ elB,
    const int* __restrict__ offC, const int* __restrict__ elC,
    const float* __restrict__ b_node, float* __restrict__ aggA,
    float* __restrict__ aggB, float* __restrict__ out_inst) {
    int w = (blockIdx.x * blockDim.x + threadIdx.x) >> 5;
    int lane = threadIdx.x & 31;

    const float* feat; const float* rs_s; const int* off; const int* el;
    float* out; int row; bool epi;
    if (w < SVC_N) {
        row = w; feat = svc_feat; rs_s = rs + OFF_A_S; off = offA; el = elA;
        out = aggA; epi = false;
    } else if (w < SVC_N + NODE_N) {
        row = w - SVC_N; feat = inst_feat; rs_s = rs + OFF_B_S; off = offB; el = elB;
        out = aggB; epi = false;
    } else if (w < SVC_N + NODE_N + INST_N) {
        row = w - SVC_N - NODE_N; feat = hC; rs_s = nullptr; off = offC; el = elC;
        out = out_inst; epi = true;
    } else return;

    int b0 = off[row];
    int b1 = off[row + 1];
    float4 acc = make_float4(0.f, 0.f, 0.f, 0.f);

    int e = b0;
    for (; e + 3 < b1; e += 4) {
        int s0 = __ldg(el + e);
        int s1 = __ldg(el + e + 1);
        int s2 = __ldg(el + e + 2);
        int s3 = __ldg(el + e + 3);
        float4 v0 = __ldg((const float4*)(feat + (size_t)s0 * HID) + lane);
        float4 v1 = __ldg((const float4*)(feat + (size_t)s1 * HID) + lane);
        float4 v2 = __ldg((const float4*)(feat + (size_t)s2 * HID) + lane);
        float4 v3 = __ldg((const float4*)(feat + (size_t)s3 * HID) + lane);
        float r0 = rs_s ? __ldg(rs_s + s0) : 1.f;
        float r1 = rs_s ? __ldg(rs_s + s1) : 1.f;
        float r2 = rs_s ? __ldg(rs_s + s2) : 1.f;
        float r3 = rs_s ? __ldg(rs_s + s3) : 1.f;
        acc.x += v0.x * r0; acc.y += v0.y * r0; acc.z += v0.z * r0; acc.w += v0.w * r0;
        acc.x += v1.x * r1; acc.y += v1.y * r1; acc.z += v1.z * r1; acc.w += v1.w * r1;
        acc.x += v2.x * r2; acc.y += v2.y * r2; acc.z += v2.z * r2; acc.w += v2.w * r2;
        acc.x += v3.x * r3; acc.y += v3.y * r3; acc.z += v3.z * r3; acc.w += v3.w * r3;
    }
    for (; e < b1; e++) {
        int s0 = __ldg(el + e);
        float4 v0 = __ldg((const float4*)(feat + (size_t)s0 * HID) + lane);
        float r0 = rs_s ? __ldg(rs_s + s0) : 1.f;
        acc.x += v0.x * r0; acc.y += v0.y * r0; acc.z += v0.z * r0; acc.w += v0.w * r0;
    }

    if (epi) {
        float rd = __ldg(rs + OFF_C_D + row);
        float4 bb = __ldg((const float4*)b_node + lane);
        acc.x = acc.x * rd + bb.x;
        acc.y = acc.y * rd + bb.y;
        acc.z = acc.z * rd + bb.z;
        acc.w = acc.w * rd + bb.w;
        acc.x = acc.x >= 0.f ? acc.x : 0.01f * acc.x;
        acc.y = acc.y >= 0.f ? acc.y : 0.01f * acc.y;
        acc.z = acc.z >= 0.f ? acc.z : 0.01f * acc.z;
        acc.w = acc.w >= 0.f ? acc.w : 0.01f * acc.w;
    }
    ((float4*)(out + (size_t)row * HID))[lane] = acc;
}

// ============================================================================
// TF32 tensor-core GEMM: out[n,128] = A[n,128] @ W[128,128]
// ============================================================================
#define AS_LD 132
#define SMEM_GEMM ((64 * AS_LD + 128 * AS_LD) * 4)

__device__ __forceinline__ float tf32_round(float v) {
    uint32_t r;
    asm("cvt.rna.tf32.f32 %0, %1;" : "=r"(r) : "f"(v));
    return __uint_as_float(r);
}

__device__ __forceinline__ void mma_tf32(float4& d, uint32_t a0, uint32_t a1,
                                         uint32_t a2, uint32_t a3,
                                         uint32_t b0, uint32_t b1) {
    asm volatile(
        "mma.sync.aligned.m16n8k8.row.col.f32.tf32.tf32.f32 "
        "{%0,%1,%2,%3}, {%4,%5,%6,%7}, {%8,%9}, {%0,%1,%2,%3};"
        : "+f"(d.x), "+f"(d.y), "+f"(d.z), "+f"(d.w)
        : "r"(a0), "r"(a1), "r"(a2), "r"(a3), "r"(b0), "r"(b1));
}

__device__ __forceinline__ void gemm_tile_tf32(
    const float* __restrict__ A, const float* __restrict__ W,
    const float* __restrict__ rs_s, const float* __restrict__ rs_d,
    const float* __restrict__ bias, float* __restrict__ out,
    int n, int base, bool prescale, bool epi, float* sm) {
    float* As = sm;                 // [64][AS_LD]
    float* Ws = sm + 64 * AS_LD;    // [128][AS_LD]
    int tid = threadIdx.x;

    for (int i = tid; i < 128 * 32; i += 256) {
        int k = i >> 5, ncol4 = (i & 31) * 4;
        float4 w = __ldg((const float4*)(W + k * HID + ncol4));
        w.x = tf32_round(w.x); w.y = tf32_round(w.y);
        w.z = tf32_round(w.z); w.w = tf32_round(w.w);
        *(float4*)&Ws[k * AS_LD + ncol4] = w;
    }
    for (int i = tid; i < 64 * 32; i += 256) {
        int r = i >> 5, k4 = (i & 31) * 4;
        int gr = base + r;
        float4 v = make_float4(0.f, 0.f, 0.f, 0.f);
        if (gr < n) {
            v = __ldg((const float4*)(A + (size_t)gr * HID + k4));
            if (prescale) {
                float rv = __ldg(rs_s + gr);
                v.x *= rv; v.y *= rv; v.z *= rv; v.w *= rv;
            }
        }
        v.x = tf32_round(v.x); v.y = tf32_round(v.y);
        v.z = tf32_round(v.z); v.w = tf32_round(v.w);
        *(float4*)&As[r * AS_LD + k4] = v;
    }
    __syncthreads();

    int warp = tid >> 5, lane = tid & 31;
    int wr = warp >> 1;
    int wc = warp & 1;
    int g = lane >> 2;
    int tig = lane & 3;

    float4 acc[8];
#pragma unroll
    for (int t = 0; t < 8; t++) acc[t] = make_float4(0.f, 0.f, 0.f, 0.f);

    int arow0 = (wr * 16 + g) * AS_LD;
    int arow1 = (wr * 16 + g + 8) * AS_LD;
    int bcol = wc * 64 + g;

#pragma unroll
    for (int k0 = 0; k0 < 128; k0 += 8) {
        uint32_t a0 = __float_as_uint(As[arow0 + k0 + tig]);
        uint32_t a1 = __float_as_uint(As[arow1 + k0 + tig]);
        uint32_t a2 = __float_as_uint(As[arow0 + k0 + tig + 4]);
        uint32_t a3 = __float_as_uint(As[arow1 + k0 + tig + 4]);
        int wk0 = (k0 + tig) * AS_LD;
        int wk1 = (k0 + tig + 4) * AS_LD;
#pragma unroll
        for (int t = 0; t < 8; t++) {
            uint32_t b0 = __float_as_uint(Ws[wk0 + bcol + t * 8]);
            uint32_t b1 = __float_as_uint(Ws[wk1 + bcol + t * 8]);
            mma_tf32(acc[t], a0, a1, a2, a3, b0, b1);
        }
    }

    int row0 = base + wr * 16 + g;
    int row1 = row0 + 8;
    float rd0 = 1.f, rd1 = 1.f;
    if (epi) {
        if (row0 < n) rd0 = __ldg(rs_d + row0);
        if (row1 < n) rd1 = __ldg(rs_d + row1);
    }
#pragma unroll
    for (int t = 0; t < 8; t++) {
        int col = wc * 64 + t * 8 + tig * 2;
        float2 lo = make_float2(acc[t].x, acc[t].y);
        float2 hi = make_float2(acc[t].z, acc[t].w);
        if (epi) {
            float bx = __ldg(bias + col), by = __ldg(bias + col + 1);
            lo.x = lo.x * rd0 + bx; lo.y = lo.y * rd0 + by;
            hi.x = hi.x * rd1 + bx; hi.y = hi.y * rd1 + by;
            lo.x = lo.x >= 0.f ? lo.x : 0.01f * lo.x;
            lo.y = lo.y >= 0.f ? lo.y : 0.01f * lo.y;
            hi.x = hi.x >= 0.f ? hi.x : 0.01f * hi.x;
            hi.y = hi.y >= 0.f ? hi.y : 0.01f * hi.y;
        }
        if (row0 < n) *(float2*)&out[(size_t)row0 * HID + col] = lo;
        if (row1 < n) *(float2*)&out[(size_t)row1 * HID + col] = hi;
    }
}

__global__ void __launch_bounds__(256) gemm_c_k(
    const float* __restrict__ A, const float* __restrict__ W,
    const float* __restrict__ rs_s, float* __restrict__ out, int n) {
    extern __shared__ float sm[];
    gemm_tile_tf32(A, W, rs_s, nullptr, nullptr, out, n, blockIdx.x * 64, true, false, sm);
}

#define NBB64 157
#define NBA64 313
__global__ void __launch_bounds__(256) gemm_ab_k(
    const float* __restrict__ aggB, const float* __restrict__ W_inst, const float* __restrict__ b_inst,
    const float* __restrict__ aggA, const float* __restrict__ W_svc, const float* __restrict__ b_svc,
    const float* __restrict__ rs, float* __restrict__ out) {
    extern __shared__ float sm[];
    if (blockIdx.x < NBB64) {
        gemm_tile_tf32(aggB, W_inst, nullptr, rs + OFF_B_D, b_inst,
                       out, NODE_N, blockIdx.x * 64, false, true, sm);
    } else {
        gemm_tile_tf32(aggA, W_svc, nullptr, rs + OFF_A_D, b_svc,
                       out + (size_t)(NODE_N + INST_N) * HID, SVC_N,
                       (blockIdx.x - NBB64) * 64, false, true, sm);
    }
}

// ============================================================================
// Host launch
// ============================================================================
extern "C" void kernel_launch(void* const* d_in, const int* in_sizes, int n_in,
                              void* d_out, int out_size) {
    const float* svc_feat  = (const float*)d_in[0];
    const float* inst_feat = (const float*)d_in[1];
    const float* node_feat = (const float*)d_in[2];
    const float* W_svc  = (const float*)d_in[3];
    const float* b_svc  = (const float*)d_in[4];
    const float* W_inst = (const float*)d_in[5];
    const float* b_inst = (const float*)d_in[6];
    const float* W_node = (const float*)d_in[7];
    const float* b_node = (const float*)d_in[8];
    const int* sc_src = (const int*)d_in[9];
    const int* sc_dst = (const int*)d_in[10];
    const int* in_src = (const int*)d_in[11];
    const int* in_dst = (const int*)d_in[12];
    const int* ni_src = (const int*)d_in[13];
    const int* ni_dst = (const int*)d_in[14];
    float* out = (float*)d_out;

    int E_sc = in_sizes[9];
    int E_in = in_sizes[11];
    int E_ni = in_sizes[13];

    int *cnt, *offA, *offB, *offC, *curA, *curB, *curC, *eA, *eB, *eC;
    float *rs, *aggA, *aggB, *hC;
    cudaGetSymbolAddress((void**)&cnt, g_cnt);
    cudaGetSymbolAddress((void**)&rs, g_rs);
    cudaGetSymbolAddress((void**)&offA, g_offA);
    cudaGetSymbolAddress((void**)&offB, g_offB);
    cudaGetSymbolAddress((void**)&offC, g_offC);
    cudaGetSymbolAddress((void**)&curA, g_curA);
    cudaGetSymbolAddress((void**)&curB, g_curB);
    cudaGetSymbolAddress((void**)&curC, g_curC);
    cudaGetSymbolAddress((void**)&eA, g_eA);
    cudaGetSymbolAddress((void**)&eB, g_eB);
    cudaGetSymbolAddress((void**)&eC, g_eC);
    cudaGetSymbolAddress((void**)&aggA, g_aggA);
    cudaGetSymbolAddress((void**)&aggB, g_aggB);
    cudaGetSymbolAddress((void**)&hC, g_hC);

    cudaFuncSetAttribute(gemm_c_k,  cudaFuncAttributeMaxDynamicSharedMemorySize, SMEM_GEMM);
    cudaFuncSetAttribute(gemm_ab_k, cudaFuncAttributeMaxDynamicSharedMemorySize, SMEM_GEMM);

    // 1) fused preamble: hist + scan + rsqrt + scatter (one persistent kernel)
    fused_pre_k<<<FBLK, FTHR>>>(sc_src, sc_dst, E_sc,
                                in_src, in_dst, E_in,
                                ni_src, ni_dst, E_ni,
                                cnt, rs, offA, offB, offC,
                                curA, curB, curC, eA, eB, eC);

    // 2) conv C GEMM (needs only rs)
    gemm_c_k<<<(NODE_N + 63) / 64, 256, SMEM_GEMM>>>(node_feat, W_node, rs + OFF_C_S, hC, NODE_N);

    // 3) all three aggregations in one launch
    int total_warps = SVC_N + NODE_N + INST_N;
    agg_all_k<<<(total_warps * 32 + 255) / 256, 256>>>(
        svc_feat, inst_feat, hC, rs,
        offA, eA, offB, eB, offC, eC,
        b_node, aggA, aggB, out + (size_t)NODE_N * HID);

    // 4) combined A+B GEMM with fused epilogue
    gemm_ab_k<<<NBB64 + NBA64, 256, SMEM_GEMM>>>(aggB, W_inst, b_inst,
                                                 aggA, W_svc, b_svc, rs, out);
}

// round 6
// speedup vs baseline: 1.2459x; 1.2459x over previous
#include <cuda_runtime.h>
#include <cstdint>

#define SVC_N  20000
#define INST_N 100000
#define NODE_N 10000
#define HID    128

#define E_SC_MAX 640000
#define E_IN_MAX 200000
#define E_NI_MAX 200000

// ---- count/rsqrt layout offsets ----
#define OFF_A_S 0
#define OFF_A_D 20000
#define OFF_B_S 40000
#define OFF_B_D 140000
#define OFF_C_S 150000
#define OFF_C_D 160000
#define CNT_TOTAL 260000

#define NB_A 20
#define NB_B 10
#define NB_C 98
#define NB_TOTAL (NB_A + NB_B + NB_C)   // 128 scan blocks
#define NB_SRC 127                       // pure-rsqrt blocks

// ---- scratch ----
__device__ int   g_cnt[CNT_TOTAL];       // zero at load; re-zeroed by scatter each run
__device__ float g_rs[CNT_TOTAL];
__device__ int   g_offA[SVC_N + 1];
__device__ int   g_offB[NODE_N + 1];
__device__ int   g_offC[INST_N + 1];
__device__ int   g_curA[SVC_N];
__device__ int   g_curB[NODE_N];
__device__ int   g_curC[INST_N];
__device__ int   g_eA[E_SC_MAX];
__device__ int   g_eB[E_IN_MAX];
__device__ int   g_eC[E_NI_MAX];
__device__ int   g_bsum[384];
__device__ int   g_bflag[384];
__device__ float g_Wr[3 * 16384];        // tf32-rounded W_svc | W_inst | W_node
__device__ float g_aggA[(size_t)SVC_N * HID];
__device__ float g_aggB[(size_t)NODE_N * HID];
__device__ float g_hC[(size_t)NODE_N * HID];

__device__ __forceinline__ float tf32_round(float v) {
    uint32_t r;
    asm("cvt.rna.tf32.f32 %0, %1;" : "=r"(r) : "f"(v));
    return __uint_as_float(r);
}

// ============================================================================
// Degree histogram (fused 3 edge lists) + flag reset + W tf32 pre-rounding
// ============================================================================
__global__ void hist_all_k(const int* __restrict__ sA, const int* __restrict__ dA, int eA,
                           const int* __restrict__ sB, const int* __restrict__ dB, int eB,
                           const int* __restrict__ sC, const int* __restrict__ dC, int eC,
                           const float* __restrict__ W_svc, const float* __restrict__ W_inst,
                           const float* __restrict__ W_node,
                           int* __restrict__ cnt, float* __restrict__ Wr) {
    int i = blockIdx.x * blockDim.x + threadIdx.x;
    if (i < 384) g_bflag[i] = 0;
    if (i < 16384)            Wr[i] = tf32_round(__ldg(W_svc + i));
    else if (i < 32768)       Wr[i] = tf32_round(__ldg(W_inst + i - 16384));
    else if (i < 49152)       Wr[i] = tf32_round(__ldg(W_node + i - 32768));
    if (i < eA) {
        atomicAdd(&cnt[OFF_A_S + sA[i]], 1);
        atomicAdd(&cnt[OFF_A_D + dA[i]], 1);
    } else if (i < eA + eB) {
        int j = i - eA;
        atomicAdd(&cnt[OFF_B_S + sB[j]], 1);
        atomicAdd(&cnt[OFF_B_D + dB[j]], 1);
    } else if (i < eA + eB + eC) {
        int j = i - eA - eB;
        atomicAdd(&cnt[OFF_C_S + sC[j]], 1);
        atomicAdd(&cnt[OFF_C_D + dC[j]], 1);
    }
}

// ============================================================================
// Fused scans (aggregate lookback) + all rsqrt norms, single kernel.
// ============================================================================
__global__ void __launch_bounds__(1024) scanrs_k(
    const int* __restrict__ cnt, float* __restrict__ rs,
    int* __restrict__ offA, int* __restrict__ offB, int* __restrict__ offC,
    int* __restrict__ curA, int* __restrict__ curB, int* __restrict__ curC,
    int eAn, int eBn, int eCn) {
    int bid = blockIdx.x, tid = threadIdx.x;

    if (bid >= NB_TOTAL) {
        int j = (bid - NB_TOTAL) * 1024 + tid;
        int idx;
        if (j < 20000)       idx = OFF_A_S + j;
        else if (j < 120000) idx = OFF_B_S + (j - 20000);
        else if (j < 130000) idx = OFF_C_S + (j - 120000);
        else return;
        int c = cnt[idx];
        rs[idx] = rsqrtf((float)(c > 0 ? c : 1));
        return;
    }

    int seg, chunk, n, E, cntoff;
    int *off, *cur;
    if (bid < NB_A)              { seg = 0; chunk = bid;               n = SVC_N;  E = eAn; cntoff = OFF_A_D; off = offA; cur = curA; }
    else if (bid < NB_A + NB_B)  { seg = 1; chunk = bid - NB_A;        n = NODE_N; E = eBn; cntoff = OFF_B_D; off = offB; cur = curB; }
    else                         { seg = 2; chunk = bid - NB_A - NB_B; n = INST_N; E = eCn; cntoff = OFF_C_D; off = offC; cur = curC; }

    int gid = chunk * 1024 + tid;
    int v = (gid < n) ? cnt[cntoff + gid] : 0;
    if (gid < n) rs[cntoff + gid] = rsqrtf((float)(v > 0 ? v : 1));

    int lane = tid & 31, w = tid >> 5;
    int x = v;
#pragma unroll
    for (int o = 1; o < 32; o <<= 1) {
        int y = __shfl_up_sync(0xffffffffu, x, o);
        if (lane >= o) x += y;
    }
    __shared__ int wsum[32];
    if (lane == 31) wsum[w] = x;
    __syncthreads();
    if (w == 0) {
        int t = wsum[lane];
#pragma unroll
        for (int o = 1; o < 32; o <<= 1) {
            int y = __shfl_up_sync(0xffffffffu, t, o);
            if (lane >= o) t += y;
        }
        wsum[lane] = t;
    }
    __syncthreads();
    int incl  = x + (w > 0 ? wsum[w - 1] : 0);
    int total = wsum[31];

    int segbase = seg * 128;
    if (tid == 0) {
        g_bsum[segbase + chunk] = total;
        __threadfence();
        atomicExch(&g_bflag[segbase + chunk], 1);
    }

    int p = 0;
    if (tid < chunk) {
        while (atomicAdd(&g_bflag[segbase + tid], 0) == 0) {}
        p = __ldcg(&g_bsum[segbase + tid]);
    }
    if (tid < 128) {
#pragma unroll
        for (int o = 16; o > 0; o >>= 1) p += __shfl_down_sync(0xffffffffu, p, o);
    }
    __shared__ int warp_p[4];
    __shared__ int s_pre;
    if (tid < 128 && lane == 0) warp_p[w] = p;
    __syncthreads();
    if (tid == 0) s_pre = warp_p[0] + warp_p[1] + warp_p[2] + warp_p[3];
    __syncthreads();
    int prefix = s_pre;

    if (gid < n) {
        int o = prefix + incl - v;
        off[gid] = o;
        cur[gid] = o;
    }
    if (chunk == 0 && tid == 0) off[n] = E;
}

// ============================================================================
// Fused scatter into dst-CSR + cnt re-zero for next graph replay
// ============================================================================
__global__ void scatter_all_k(const int* __restrict__ sA, const int* __restrict__ dA, int eA,
                              const int* __restrict__ sB, const int* __restrict__ dB, int eB,
                              const int* __restrict__ sC, const int* __restrict__ dC, int eC,
                              int* __restrict__ curA, int* __restrict__ curB, int* __restrict__ curC,
                              int* __restrict__ elA, int* __restrict__ elB, int* __restrict__ elC,
                              int* __restrict__ cnt) {
    int i = blockIdx.x * blockDim.x + threadIdx.x;
    if (i < CNT_TOTAL) cnt[i] = 0;
    if (i < eA) {
        int p = atomicAdd(&curA[dA[i]], 1);
        elA[p] = sA[i];
    } else if (i < eA + eB) {
        int j = i - eA;
        int p = atomicAdd(&curB[dB[j]], 1);
        elB[p] = sB[j];
    } else if (i < eA + eB + eC) {
        int j = i - eA - eB;
        int p = atomicAdd(&curC[dC[j]], 1);
        elC[p] = sC[j];
    }
}

// ============================================================================
// Combined aggregation (tf32-rounds the GEMM-bound outputs in epilogue)
// ============================================================================
__global__ void __launch_bounds__(256) agg_all_k(
    const float* __restrict__ svc_feat, const float* __restrict__ inst_feat,
    const float* __restrict__ hC, const float* __restrict__ rs,
    const int* __restrict__ offA, const int* __restrict__ elA,
    const int* __restrict__ offB, const int* __restrict__ elB,
    const int* __restrict__ offC, const int* __restrict__ elC,
    const float* __restrict__ b_node, float* __restrict__ aggA,
    float* __restrict__ aggB, float* __restrict__ out_inst) {
    int w = (blockIdx.x * blockDim.x + threadIdx.x) >> 5;
    int lane = threadIdx.x & 31;

    const float* feat; const float* rs_s; const int* off; const int* el;
    float* out; int row; bool epi;
    if (w < SVC_N) {
        row = w; feat = svc_feat; rs_s = rs + OFF_A_S; off = offA; el = elA;
        out = aggA; epi = false;
    } else if (w < SVC_N + NODE_N) {
        row = w - SVC_N; feat = inst_feat; rs_s = rs + OFF_B_S; off = offB; el = elB;
        out = aggB; epi = false;
    } else if (w < SVC_N + NODE_N + INST_N) {
        row = w - SVC_N - NODE_N; feat = hC; rs_s = nullptr; off = offC; el = elC;
        out = out_inst; epi = true;
    } else return;

    int b0 = off[row];
    int b1 = off[row + 1];
    float4 acc = make_float4(0.f, 0.f, 0.f, 0.f);

    int e = b0;
    for (; e + 3 < b1; e += 4) {
        int s0 = __ldg(el + e);
        int s1 = __ldg(el + e + 1);
        int s2 = __ldg(el + e + 2);
        int s3 = __ldg(el + e + 3);
        float4 v0 = __ldg((const float4*)(feat + (size_t)s0 * HID) + lane);
        float4 v1 = __ldg((const float4*)(feat + (size_t)s1 * HID) + lane);
        float4 v2 = __ldg((const float4*)(feat + (size_t)s2 * HID) + lane);
        float4 v3 = __ldg((const float4*)(feat + (size_t)s3 * HID) + lane);
        float r0 = rs_s ? __ldg(rs_s + s0) : 1.f;
        float r1 = rs_s ? __ldg(rs_s + s1) : 1.f;
        float r2 = rs_s ? __ldg(rs_s + s2) : 1.f;
        float r3 = rs_s ? __ldg(rs_s + s3) : 1.f;
        acc.x += v0.x * r0; acc.y += v0.y * r0; acc.z += v0.z * r0; acc.w += v0.w * r0;
        acc.x += v1.x * r1; acc.y += v1.y * r1; acc.z += v1.z * r1; acc.w += v1.w * r1;
        acc.x += v2.x * r2; acc.y += v2.y * r2; acc.z += v2.z * r2; acc.w += v2.w * r2;
        acc.x += v3.x * r3; acc.y += v3.y * r3; acc.z += v3.z * r3; acc.w += v3.w * r3;
    }
    for (; e < b1; e++) {
        int s0 = __ldg(el + e);
        float4 v0 = __ldg((const float4*)(feat + (size_t)s0 * HID) + lane);
        float r0 = rs_s ? __ldg(rs_s + s0) : 1.f;
        acc.x += v0.x * r0; acc.y += v0.y * r0; acc.z += v0.z * r0; acc.w += v0.w * r0;
    }

    if (epi) {
        float rd = __ldg(rs + OFF_C_D + row);
        float4 bb = __ldg((const float4*)b_node + lane);
        acc.x = acc.x * rd + bb.x;
        acc.y = acc.y * rd + bb.y;
        acc.z = acc.z * rd + bb.z;
        acc.w = acc.w * rd + bb.w;
        acc.x = acc.x >= 0.f ? acc.x : 0.01f * acc.x;
        acc.y = acc.y >= 0.f ? acc.y : 0.01f * acc.y;
        acc.z = acc.z >= 0.f ? acc.z : 0.01f * acc.z;
        acc.w = acc.w >= 0.f ? acc.w : 0.01f * acc.w;
    } else {
        // pre-round for the downstream tf32 GEMM (numerics identical to
        // rounding at GEMM staging time)
        acc.x = tf32_round(acc.x); acc.y = tf32_round(acc.y);
        acc.z = tf32_round(acc.z); acc.w = tf32_round(acc.w);
    }
    ((float4*)(out + (size_t)row * HID))[lane] = acc;
}

// ============================================================================
// TF32 tensor-core GEMM, cp.async staging, pre-rounded operands.
// Block: 64 rows x 128 cols, 256 threads. Ws stride 136, As stride 132
// (both conflict-free for the fragment access patterns).
// ============================================================================
#define WS_LD 136
#define ASL   132
#define SMEM_GEMM (128 * WS_LD * 4 + 64 * ASL * 4)   // 103424 B -> 2 blocks/SM

__device__ __forceinline__ void cp16(uint32_t s, const void* g) {
    asm volatile("cp.async.cg.shared.global [%0], [%1], 16;" :: "r"(s), "l"(g));
}
#define CP_COMMIT() asm volatile("cp.async.commit_group;")
#define CP_WAIT0()  asm volatile("cp.async.wait_group 0;")

__device__ __forceinline__ void mma_tf32(float4& d, uint32_t a0, uint32_t a1,
                                         uint32_t a2, uint32_t a3,
                                         uint32_t b0, uint32_t b1) {
    asm volatile(
        "mma.sync.aligned.m16n8k8.row.col.f32.tf32.tf32.f32 "
        "{%0,%1,%2,%3}, {%4,%5,%6,%7}, {%8,%9}, {%0,%1,%2,%3};"
        : "+f"(d.x), "+f"(d.y), "+f"(d.z), "+f"(d.w)
        : "r"(a0), "r"(a1), "r"(a2), "r"(a3), "r"(b0), "r"(b1));
}

// Compute + store one 64x128 tile from staged smem. No internal syncthreads.
__device__ __forceinline__ void gemm_compute_store(
    const float* __restrict__ Ws, const float* __restrict__ As,
    const float* __restrict__ rs_d, const float* __restrict__ bias,
    float* __restrict__ out, int n, int base, bool epi) {
    int tid = threadIdx.x;
    int warp = tid >> 5, lane = tid & 31;
    int wr = warp >> 1;
    int wc = warp & 1;
    int g = lane >> 2;
    int tig = lane & 3;

    float4 acc[8];
#pragma unroll
    for (int t = 0; t < 8; t++) acc[t] = make_float4(0.f, 0.f, 0.f, 0.f);

    int arow0 = (wr * 16 + g) * ASL;
    int arow1 = (wr * 16 + g + 8) * ASL;
    int bcol = wc * 64 + g;

#pragma unroll
    for (int k0 = 0; k0 < 128; k0 += 8) {
        uint32_t a0 = __float_as_uint(As[arow0 + k0 + tig]);
        uint32_t a1 = __float_as_uint(As[arow1 + k0 + tig]);
        uint32_t a2 = __float_as_uint(As[arow0 + k0 + tig + 4]);
        uint32_t a3 = __float_as_uint(As[arow1 + k0 + tig + 4]);
        int wk0 = (k0 + tig) * WS_LD;
        int wk1 = (k0 + tig + 4) * WS_LD;
#pragma unroll
        for (int t = 0; t < 8; t++) {
            uint32_t b0 = __float_as_uint(Ws[wk0 + bcol + t * 8]);
            uint32_t b1 = __float_as_uint(Ws[wk1 + bcol + t * 8]);
            mma_tf32(acc[t], a0, a1, a2, a3, b0, b1);
        }
    }

    int row0 = base + wr * 16 + g;
    int row1 = row0 + 8;
    float rd0 = 1.f, rd1 = 1.f;
    if (epi) {
        if (row0 < n) rd0 = __ldg(rs_d + row0);
        if (row1 < n) rd1 = __ldg(rs_d + row1);
    }
#pragma unroll
    for (int t = 0; t < 8; t++) {
        int col = wc * 64 + t * 8 + tig * 2;
        float2 lo = make_float2(acc[t].x, acc[t].y);
        float2 hi = make_float2(acc[t].z, acc[t].w);
        if (epi) {
            float bx = __ldg(bias + col), by = __ldg(bias + col + 1);
            lo.x = lo.x * rd0 + bx; lo.y = lo.y * rd0 + by;
            hi.x = hi.x * rd1 + bx; hi.y = hi.y * rd1 + by;
            lo.x = lo.x >= 0.f ? lo.x : 0.01f * lo.x;
            lo.y = lo.y >= 0.f ? lo.y : 0.01f * lo.y;
            hi.x = hi.x >= 0.f ? hi.x : 0.01f * hi.x;
            hi.y = hi.y >= 0.f ? hi.y : 0.01f * hi.y;
        }
        if (row0 < n) *(float2*)&out[(size_t)row0 * HID + col] = lo;
        if (row1 < n) *(float2*)&out[(size_t)row1 * HID + col] = hi;
    }
}

__device__ __forceinline__ void stage_W_async(float* Ws, const float* __restrict__ Wr) {
    uint32_t base = (uint32_t)__cvta_generic_to_shared(Ws);
    int tid = threadIdx.x;
    for (int i = tid; i < 128 * 32; i += 256) {
        int k = i >> 5, c4 = (i & 31) * 4;
        cp16(base + (k * WS_LD + c4) * 4, Wr + k * HID + c4);
    }
}

__device__ __forceinline__ void stage_A_async(float* As, const float* __restrict__ A,
                                              int base_row, int n) {
    uint32_t sb = (uint32_t)__cvta_generic_to_shared(As);
    int tid = threadIdx.x;
    for (int i = tid; i < 64 * 32; i += 256) {
        int r = i >> 5, c4 = (i & 31) * 4;
        int gr = base_row + r;
        if (gr < n)
            cp16(sb + (r * ASL + c4) * 4, A + (size_t)gr * HID + c4);
        else
            *(float4*)&As[r * ASL + c4] = make_float4(0.f, 0.f, 0.f, 0.f);
    }
}

// Conv C GEMM: node_feat prescaled+rounded at staging (no cp.async on A).
__global__ void __launch_bounds__(256) gemm_c_k(
    const float* __restrict__ A, const float* __restrict__ Wr,
    const float* __restrict__ rs_s, float* __restrict__ out, int n) {
    extern __shared__ float sm[];
    float* Ws = sm;
    float* As = sm + 128 * WS_LD;
    int tid = threadIdx.x;
    int base = blockIdx.x * 64;

    stage_W_async(Ws, Wr);
    CP_COMMIT();
    for (int i = tid; i < 64 * 32; i += 256) {
        int r = i >> 5, c4 = (i & 31) * 4;
        int gr = base + r;
        float4 v = make_float4(0.f, 0.f, 0.f, 0.f);
        if (gr < n) {
            v = __ldg((const float4*)(A + (size_t)gr * HID + c4));
            float rv = __ldg(rs_s + gr);
            v.x = tf32_round(v.x * rv); v.y = tf32_round(v.y * rv);
            v.z = tf32_round(v.z * rv); v.w = tf32_round(v.w * rv);
        }
        *(float4*)&As[r * ASL + c4] = v;
    }
    CP_WAIT0();
    __syncthreads();
    gemm_compute_store(Ws, As, nullptr, nullptr, out, n, base, false);
}

// Combined A+B GEMM: persistent W per block, block-strided tile loop.
#define GAB_GRID 296
#define GAB_BSPLIT 98        // blocks [0,98) -> conv B (157 tiles); rest -> conv A (313 tiles)
#define TILES_B 157
#define TILES_A 313
__global__ void __launch_bounds__(256) gemm_ab_k(
    const float* __restrict__ aggB, const float* __restrict__ Wi_r, const float* __restrict__ b_inst,
    const float* __restrict__ aggA, const float* __restrict__ Ws_r, const float* __restrict__ b_svc,
    const float* __restrict__ rs, float* __restrict__ out) {
    extern __shared__ float sm[];
    float* Ws = sm;
    float* As = sm + 128 * WS_LD;

    const float *A, *Wr, *bias, *rs_d;
    float* o; int n, tile0, tstride, ntiles;
    if (blockIdx.x < GAB_BSPLIT) {
        A = aggB; Wr = Wi_r; bias = b_inst; rs_d = rs + OFF_B_D;
        o = out; n = NODE_N;
        tile0 = blockIdx.x; tstride = GAB_BSPLIT; ntiles = TILES_B;
    } else {
        A = aggA; Wr = Ws_r; bias = b_svc; rs_d = rs + OFF_A_D;
        o = out + (size_t)(NODE_N + INST_N) * HID; n = SVC_N;
        tile0 = blockIdx.x - GAB_BSPLIT; tstride = GAB_GRID - GAB_BSPLIT; ntiles = TILES_A;
    }

    stage_W_async(Ws, Wr);
    bool first = true;
    for (int t = tile0; t < ntiles; t += tstride) {
        if (!first) __syncthreads();          // all reads of As done
        stage_A_async(As, A, t * 64, n);
        CP_COMMIT();
        CP_WAIT0();
        __syncthreads();
        gemm_compute_store(Ws, As, rs_d, bias, o, n, t * 64, true);
        first = false;
    }
}

// ============================================================================
// Host launch
// ============================================================================
extern "C" void kernel_launch(void* const* d_in, const int* in_sizes, int n_in,
                              void* d_out, int out_size) {
    const float* svc_feat  = (const float*)d_in[0];
    const float* inst_feat = (const float*)d_in[1];
    const float* node_feat = (const float*)d_in[2];
    const float* W_svc  = (const float*)d_in[3];
    const float* b_svc  = (const float*)d_in[4];
    const float* W_inst = (const float*)d_in[5];
    const float* b_inst = (const float*)d_in[6];
    const float* W_node = (const float*)d_in[7];
    const float* b_node = (const float*)d_in[8];
    const int* sc_src = (const int*)d_in[9];
    const int* sc_dst = (const int*)d_in[10];
    const int* in_src = (const int*)d_in[11];
    const int* in_dst = (const int*)d_in[12];
    const int* ni_src = (const int*)d_in[13];
    const int* ni_dst = (const int*)d_in[14];
    float* out = (float*)d_out;

    int E_sc = in_sizes[9];
    int E_in = in_sizes[11];
    int E_ni = in_sizes[13];
    int E_tot = E_sc + E_in + E_ni;

    int *cnt, *offA, *offB, *offC, *curA, *curB, *curC, *eA, *eB, *eC;
    float *rs, *aggA, *aggB, *hC, *Wr;
    cudaGetSymbolAddress((void**)&cnt, g_cnt);
    cudaGetSymbolAddress((void**)&rs, g_rs);
    cudaGetSymbolAddress((void**)&offA, g_offA);
    cudaGetSymbolAddress((void**)&offB, g_offB);
    cudaGetSymbolAddress((void**)&offC, g_offC);
    cudaGetSymbolAddress((void**)&curA, g_curA);
    cudaGetSymbolAddress((void**)&curB, g_curB);
    cudaGetSymbolAddress((void**)&curC, g_curC);
    cudaGetSymbolAddress((void**)&eA, g_eA);
    cudaGetSymbolAddress((void**)&eB, g_eB);
    cudaGetSymbolAddress((void**)&eC, g_eC);
    cudaGetSymbolAddress((void**)&aggA, g_aggA);
    cudaGetSymbolAddress((void**)&aggB, g_aggB);
    cudaGetSymbolAddress((void**)&hC, g_hC);
    cudaGetSymbolAddress((void**)&Wr, g_Wr);

    cudaFuncSetAttribute(gemm_c_k,  cudaFuncAttributeMaxDynamicSharedMemorySize, SMEM_GEMM);
    cudaFuncSetAttribute(gemm_ab_k, cudaFuncAttributeMaxDynamicSharedMemorySize, SMEM_GEMM);

    // 1) degrees + flag reset + W pre-rounding
    hist_all_k<<<(E_tot + 255) / 256, 256>>>(sc_src, sc_dst, E_sc,
                                             in_src, in_dst, E_in,
                                             ni_src, ni_dst, E_ni,
                                             W_svc, W_inst, W_node, cnt, Wr);

    // 2) fused scans + all rsqrt norms
    scanrs_k<<<NB_TOTAL + NB_SRC, 1024>>>(cnt, rs, offA, offB, offC,
                                          curA, curB, curC, E_sc, E_in, E_ni);

    // 3) conv C GEMM (needs only rs + rounded W_node)
    gemm_c_k<<<(NODE_N + 63) / 64, 256, SMEM_GEMM>>>(node_feat, Wr + 32768,
                                                     rs + OFF_C_S, hC, NODE_N);

    // 4) scatter into CSR (+ cnt re-zero)
    scatter_all_k<<<(E_tot + 255) / 256, 256>>>(sc_src, sc_dst, E_sc,
                                                in_src, in_dst, E_in,
                                                ni_src, ni_dst, E_ni,
                                                curA, curB, curC, eA, eB, eC, cnt);

    // 5) all three aggregations (A/B outputs pre-rounded for the GEMM)
    int total_warps = SVC_N + NODE_N + INST_N;
    agg_all_k<<<(total_warps * 32 + 255) / 256, 256>>>(
        svc_feat, inst_feat, hC, rs,
        offA, eA, offB, eB, offC, eC,
        b_node, aggA, aggB, out + (size_t)NODE_N * HID);

    // 6) combined A+B GEMM, persistent W, cp.async staging
    gemm_ab_k<<<GAB_GRID, 256, SMEM_GEMM>>>(aggB, Wr + 16384, b_inst,
                                            aggA, Wr, b_svc, rs, out);
}